// round 12
// baseline (speedup 1.0000x reference)
#include <cuda_runtime.h>

// PairWiseRankingLoss, closed form.
// gama=1, p=sigmoid(x) in (0,1)  =>  1 + p_i - p_j > 0 for every pair, so relu
// never clips and the masked pair-sum factorizes per row:
//   loss_b = n0*n1*gama + n1*sum_{y=0} p - n0*sum_{y=1} p
// Total = sum_b loss_b.
//
// Measured-optimal shape: 128 CTAs x 256 threads, one row per CTA, 4 elems/thread
// (2x LDG.128). Departures (16x1024, 128x128x8elem) both regressed.
// Cross-block combine: ONE u64 atomicAdd per block into g_acc, packing
//   [63:56] block-arrival count, [55:0] fixed-point (x1024) loss sum.
// The pre-add return value tells each block whether it's last AND the sum of
// all other blocks -- no ticket atomic, no fence, no read-back. Atomics on a
// single address are totally ordered, so no further sync is needed. Integer
// accumulation makes the output bit-deterministic across replays.

#define B_ROWS   128
#define L_COLS   1024
#define NTHREADS 256   // 256 threads * 4 elems = 1024 = one row per block

#define CNT_SHIFT 56
#define LOW_MASK  ((1ULL << CNT_SHIFT) - 1ULL)
#define FIX_SCALE 1024.0f

__device__ unsigned long long g_acc;   // zero at load; winner rearms each launch

__global__ void __launch_bounds__(NTHREADS)
prl_kernel(const float* __restrict__ logit,
           const int*   __restrict__ y,
           float*       __restrict__ out)
{
    const int b   = blockIdx.x;
    const int t   = threadIdx.x;
    const int wid = t >> 5, lid = t & 31;

    // Vectorized coalesced loads: 4 consecutive elements per thread.
    const float4 lv = reinterpret_cast<const float4*>(logit + b * L_COLS)[t];
    const int4   yv = reinterpret_cast<const int4*>(y + b * L_COLS)[t];

    // Branchless: sa = sum p, sp = sum y*p, cnt = sum y.
    float sa = 0.f, sp = 0.f;
    int cnt;
    {
        float p;
        p = 1.f / (1.f + __expf(-lv.x)); sa += p; sp = fmaf((float)yv.x, p, sp);
        p = 1.f / (1.f + __expf(-lv.y)); sa += p; sp = fmaf((float)yv.y, p, sp);
        p = 1.f / (1.f + __expf(-lv.z)); sa += p; sp = fmaf((float)yv.z, p, sp);
        p = 1.f / (1.f + __expf(-lv.w)); sa += p; sp = fmaf((float)yv.w, p, sp);
        cnt = yv.x + yv.y + yv.z + yv.w;
    }

    // Warp reduce: two interleaved float shuffle chains + one REDUX for the count.
    #pragma unroll
    for (int off = 16; off > 0; off >>= 1) {
        sa += __shfl_down_sync(0xffffffffu, sa, off);
        sp += __shfl_down_sync(0xffffffffu, sp, off);
    }
    cnt = __reduce_add_sync(0xffffffffu, cnt);

    __shared__ float s_a[8], s_p[8];
    __shared__ int   s_c[8];
    if (lid == 0) { s_a[wid] = sa; s_p[wid] = sp; s_c[wid] = cnt; }
    __syncthreads();

    // Warp 0: reduce the 8 per-warp partials, lane 0 finishes.
    if (wid == 0) {
        float a  = (lid < 8) ? s_a[lid] : 0.f;
        float pp = (lid < 8) ? s_p[lid] : 0.f;
        int   cc = (lid < 8) ? s_c[lid] : 0;
        #pragma unroll
        for (int off = 4; off > 0; off >>= 1) {
            a  += __shfl_down_sync(0xffffffffu, a,  off);
            pp += __shfl_down_sync(0xffffffffu, pp, off);
        }
        cc = __reduce_add_sync(0xffffffffu, cc);

        if (lid == 0) {
            const float c1 = (float)cc;
            const float c0 = (float)(L_COLS - cc);
            const float sneg = a - pp;
            // row loss = c0*c1*gama + c1*sum_neg - c0*sum_pos   (gama = 1)
            const float rowloss = fmaf(c1, sneg, fmaf(-c0, pp, c0 * c1));

            // Pack: arrival count in [63:56], fixed-point (x1024) loss in [55:0].
            // rowloss in [0, ~3e5]; 128-row sum ~2^45 << 2^56, no overflow.
            const unsigned long long contrib =
                (1ULL << CNT_SHIFT) |
                (unsigned long long)__float2ull_rn(rowloss * FIX_SCALE);

            const unsigned long long old = atomicAdd(&g_acc, contrib);
            if ((old >> CNT_SHIFT) == (unsigned long long)(B_ROWS - 1)) {
                // Pre-add value held the other 127 contributions; add ours.
                const unsigned long long tot = (old + contrib) & LOW_MASK;
                *out = (float)((double)tot * (1.0 / (double)FIX_SCALE));
                g_acc = 0ULL;   // rearm for next graph replay (no writers remain)
            }
        }
    }
}

extern "C" void kernel_launch(void* const* d_in, const int* in_sizes, int n_in,
                              void* d_out, int out_size)
{
    const float* logit = (const float*)d_in[0];
    const int*   y     = (const int*)d_in[1];
    float*       out   = (float*)d_out;
    (void)in_sizes; (void)n_in; (void)out_size;

    prl_kernel<<<B_ROWS, NTHREADS>>>(logit, y, out);
}

// round 13
// speedup vs baseline: 1.0197x; 1.0197x over previous
#include <cuda_runtime.h>

// PairWiseRankingLoss, closed form.
// gama=1, p=sigmoid(x) in (0,1)  =>  1 + p_i - p_j > 0 for every pair, so relu
// never clips and the masked pair-sum factorizes per row:
//   loss_b = n0*n1*gama + n1*sum_{y=0} p - n0*sum_{y=1} p
// Total = sum_b loss_b.
//
// Measured-optimal shape: 128 CTAs x 256 threads, one row per CTA, 4 elems/thread
// (2x LDG.128). Departures (16x1024, 128x128x8elem) both regressed.
// Cross-block combine: ONE u64 atomicAdd per block into g_acc, packing
//   [63:56] block-arrival count, [55:0] fixed-point (x1024) loss sum.
// The pre-add return value tells each block whether it's last AND the sum of
// all other blocks -- no ticket atomic, no fence, no read-back. Atomics on a
// single address are totally ordered, so no further sync is needed. Integer
// accumulation makes the output bit-deterministic across replays.

#define B_ROWS   128
#define L_COLS   1024
#define NTHREADS 256   // 256 threads * 4 elems = 1024 = one row per block

#define CNT_SHIFT 56
#define LOW_MASK  ((1ULL << CNT_SHIFT) - 1ULL)
#define FIX_SCALE 1024.0f

__device__ unsigned long long g_acc;   // zero at load; winner rearms each launch

__global__ void __launch_bounds__(NTHREADS)
prl_kernel(const float* __restrict__ logit,
           const int*   __restrict__ y,
           float*       __restrict__ out)
{
    const int b   = blockIdx.x;
    const int t   = threadIdx.x;
    const int wid = t >> 5, lid = t & 31;

    // Vectorized coalesced loads: 4 consecutive elements per thread.
    const float4 lv = reinterpret_cast<const float4*>(logit + b * L_COLS)[t];
    const int4   yv = reinterpret_cast<const int4*>(y + b * L_COLS)[t];

    // Branchless: sa = sum p, sp = sum y*p, cnt = sum y.
    float sa = 0.f, sp = 0.f;
    int cnt;
    {
        float p;
        p = 1.f / (1.f + __expf(-lv.x)); sa += p; sp = fmaf((float)yv.x, p, sp);
        p = 1.f / (1.f + __expf(-lv.y)); sa += p; sp = fmaf((float)yv.y, p, sp);
        p = 1.f / (1.f + __expf(-lv.z)); sa += p; sp = fmaf((float)yv.z, p, sp);
        p = 1.f / (1.f + __expf(-lv.w)); sa += p; sp = fmaf((float)yv.w, p, sp);
        cnt = yv.x + yv.y + yv.z + yv.w;
    }

    // Warp reduce: two interleaved float shuffle chains + one REDUX for the count.
    #pragma unroll
    for (int off = 16; off > 0; off >>= 1) {
        sa += __shfl_down_sync(0xffffffffu, sa, off);
        sp += __shfl_down_sync(0xffffffffu, sp, off);
    }
    cnt = __reduce_add_sync(0xffffffffu, cnt);

    __shared__ float s_a[8], s_p[8];
    __shared__ int   s_c[8];
    if (lid == 0) { s_a[wid] = sa; s_p[wid] = sp; s_c[wid] = cnt; }
    __syncthreads();

    // Warp 0: reduce the 8 per-warp partials, lane 0 finishes.
    if (wid == 0) {
        float a  = (lid < 8) ? s_a[lid] : 0.f;
        float pp = (lid < 8) ? s_p[lid] : 0.f;
        int   cc = (lid < 8) ? s_c[lid] : 0;
        #pragma unroll
        for (int off = 4; off > 0; off >>= 1) {
            a  += __shfl_down_sync(0xffffffffu, a,  off);
            pp += __shfl_down_sync(0xffffffffu, pp, off);
        }
        cc = __reduce_add_sync(0xffffffffu, cc);

        if (lid == 0) {
            const float c1 = (float)cc;
            const float c0 = (float)(L_COLS - cc);
            const float sneg = a - pp;
            // row loss = c0*c1*gama + c1*sum_neg - c0*sum_pos   (gama = 1)
            const float rowloss = fmaf(c1, sneg, fmaf(-c0, pp, c0 * c1));

            // Pack: arrival count in [63:56], fixed-point (x1024) loss in [55:0].
            // rowloss in [0, ~3e5]; 128-row sum ~2^45 << 2^56, no overflow.
            const unsigned long long contrib =
                (1ULL << CNT_SHIFT) |
                (unsigned long long)__float2ull_rn(rowloss * FIX_SCALE);

            const unsigned long long old = atomicAdd(&g_acc, contrib);
            if ((old >> CNT_SHIFT) == (unsigned long long)(B_ROWS - 1)) {
                // Pre-add value held the other 127 contributions; add ours.
                const unsigned long long tot = (old + contrib) & LOW_MASK;
                *out = (float)((double)tot * (1.0 / (double)FIX_SCALE));
                g_acc = 0ULL;   // rearm for next graph replay (no writers remain)
            }
        }
    }
}

extern "C" void kernel_launch(void* const* d_in, const int* in_sizes, int n_in,
                              void* d_out, int out_size)
{
    const float* logit = (const float*)d_in[0];
    const int*   y     = (const int*)d_in[1];
    float*       out   = (float*)d_out;
    (void)in_sizes; (void)n_in; (void)out_size;

    prl_kernel<<<B_ROWS, NTHREADS>>>(logit, y, out);
}